// round 14
// baseline (speedup 1.0000x reference)
#include <cuda_runtime.h>
#include <cuda_fp16.h>

// MKMMD loss, fused persistent kernel (R14 = R9 design at 512 threads/CTA:
// 2x1 pairs/thread, 4 warps/SMSP for latency hiding; zero structural change
// otherwise). 136 CTAs, one 32x32 pair tile each, full D=512, half2 math,
// fp16 accum flushed to fp32 every 64 k, distances register-resident across
// the device barrier, exp from registers.
// total = concat(src,tgt): N=512 rows, D=512.
// result = (10*N + 2*sum_{i<j} s_i s_j (kL2+kL1)) / B^2, s=+/-1 by half.
// bw_x = 2*S_upper_x/(N^2-N)/100 ; k = sum_{m=0..4} exp(-d/(bw*10^m))

#define DDIM    512
#define NTIL    16
#define GRID    136
#define NTHREAD 512
#define CH      64        // k-values per chunk (fp16 accum chain length)
#define SWH     36        // row stride in half2 units: 144B = 9*16B (odd) ->
                          // conflict-free LDS.128, 16B-aligned rows

__device__ float g_p1[GRID];
__device__ float g_p2[GRID];
__device__ float g_p3[GRID];
__device__ int   g_bar1;
__device__ int   g_bar2;

// fused block reduce of two floats (512 thr); valid on thread 0 only
__device__ __forceinline__ void bred2(float& x, float& y, float* sbuf) {
    const int tid = threadIdx.x;
#pragma unroll
    for (int o = 16; o; o >>= 1) {
        x += __shfl_down_sync(0xffffffffu, x, o);
        y += __shfl_down_sync(0xffffffffu, y, o);
    }
    __syncthreads();                 // protect sbuf reuse across calls
    if ((tid & 31) == 0) {
        sbuf[2 * (tid >> 5)]     = x;
        sbuf[2 * (tid >> 5) + 1] = y;
    }
    __syncthreads();
    if (tid == 0) {
        float rx = 0.0f, ry = 0.0f;
#pragma unroll
        for (int w = 0; w < 16; ++w) { rx += sbuf[2 * w]; ry += sbuf[2 * w + 1]; }
        x = rx; y = ry;
    }
}

// single-value block reduce (512 thr); valid on thread 0 only
__device__ __forceinline__ float bred(float v, float* sbuf) {
    const int tid = threadIdx.x;
#pragma unroll
    for (int o = 16; o; o >>= 1) v += __shfl_down_sync(0xffffffffu, v, o);
    __syncthreads();
    if ((tid & 31) == 0) sbuf[tid >> 5] = v;
    __syncthreads();
    float r = 0.0f;
    if (tid == 0) {
#pragma unroll
        for (int w = 0; w < 16; ++w) r += sbuf[w];
    }
    return r;
}

__device__ __forceinline__ unsigned pk(float x, float y) {
    __half2 h = __floats2half2_rn(x, y);
    return *reinterpret_cast<unsigned*>(&h);
}
__device__ __forceinline__ __half2 uph(unsigned u) {
    return *reinterpret_cast<__half2*>(&u);
}

__global__ __launch_bounds__(NTHREAD, 1) void mkmmd_kernel(
    const float* __restrict__ src, const float* __restrict__ tgt,
    float* __restrict__ out)
{
    __shared__ __align__(16) unsigned As[2][32][SWH];   // half2 elements
    __shared__ __align__(16) unsigned Bs[2][32][SWH];
    __shared__ float sbuf[32];
    __shared__ float siv[10];       // NEGATED inverse-bandwidth ladders
    __shared__ int   winflag;

    const int tid = threadIdx.x;
    const int tx = tid & 15;        // B column 0..15 (pairs tx, tx+16)
    const int ty = tid >> 4;        // A row 0..31

    // decode upper-triangle tile (ti <= tj) over 16x16 grid of 32x32 tiles
    int t = blockIdx.x, ti = 0;
    while (t >= NTIL - ti) { t -= NTIL - ti; ti++; }
    const int tj = ti + t;
    const int i0 = ti * 32, j0 = tj * 32;
    const float* Ap = (i0 < 256) ? src + (size_t)i0 * DDIM : tgt + (size_t)(i0 - 256) * DDIM;
    const float* Bp = (j0 < 256) ? src + (size_t)j0 * DDIM : tgt + (size_t)(j0 - 256) * DDIM;

    // load assignment: row lr (0..31), 4 floats (-> 2 half2) at lcf
    const int lr  = tid >> 4;
    const int lcf = (tid & 15) * 4;       // float offset within 64-wide chunk
    const int lch = (tid & 15) * 2;       // half2 offset in smem row

    float l1a[2] = {0.f, 0.f};
    float l2a[2] = {0.f, 0.f};

    float4 pa = *(const float4*)(Ap + (size_t)lr * DDIM + lcf);
    float4 pb = *(const float4*)(Bp + (size_t)lr * DDIM + lcf);

    const int NCHUNK = DDIM / CH;   // 8
    for (int c = 0; c < NCHUNK; ++c) {
        const int p = c & 1;
        // convert prefetched floats to half2, one STS.64 per matrix
        {
            uint2 ua = make_uint2(pk(pa.x, pa.y), pk(pa.z, pa.w));
            uint2 ub = make_uint2(pk(pb.x, pb.y), pk(pb.z, pb.w));
            *(uint2*)&As[p][lr][lch] = ua;
            *(uint2*)&Bs[p][lr][lch] = ub;
        }
        __syncthreads();   // also guarantees compute(c-1) done before next STS

        if (c < NCHUNK - 1) {
            const int kb = (c + 1) * CH;
            pa = *(const float4*)(Ap + (size_t)lr * DDIM + kb + lcf);
            pb = *(const float4*)(Bp + (size_t)lr * DDIM + kb + lcf);
        }

        // fp16 chunk accumulators (chain length 64 adds, values << 65504)
        __half2 h1[2], h2[2];
        const __half2 hz = __float2half2_rn(0.0f);
        h1[0] = hz; h1[1] = hz; h2[0] = hz; h2[1] = hz;

        const uint4* ap  = (const uint4*)&As[p][ty][0];
        const uint4* b0p = (const uint4*)&Bs[p][tx][0];
        const uint4* b1p = (const uint4*)&Bs[p][tx + 16][0];

#pragma unroll
        for (int q = 0; q < CH / 8; ++q) {     // 8 k per q via LDS.128
            uint4 A0 = ap[q], B0 = b0p[q], B1 = b1p[q];
            const unsigned au[4] = {A0.x, A0.y, A0.z, A0.w};
            const unsigned bu0[4] = {B0.x, B0.y, B0.z, B0.w};
            const unsigned bu1[4] = {B1.x, B1.y, B1.z, B1.w};
#pragma unroll
            for (int h = 0; h < 4; ++h) {      // 2 k per h
                __half2 av = uph(au[h]);
                __half2 bv[2] = {uph(bu0[h]), uph(bu1[h])};
#pragma unroll
                for (int v = 0; v < 2; ++v) {
                    __half2 d = __hsub2(av, bv[v]);       // HADD2 (fma)
                    h1[v] = __hadd2(h1[v], __habs2(d));   // LOP3 + HADD2
                    h2[v] = __hfma2(d, d, h2[v]);         // HFMA2 (fma)
                }
            }
        }

        // flush chunk accumulators to fp32
#pragma unroll
        for (int v = 0; v < 2; ++v) {
            float2 f1 = __half22float2(h1[v]);
            float2 f2 = __half22float2(h2[v]);
            l1a[v] += f1.x + f1.y;
            l2a[v] += f2.x + f2.y;
        }
    }

    // masked upper-triangle partial sums for bandwidth (dist stay in regs)
    bool keep[2];
    float s1 = 0.0f, s2 = 0.0f;
#pragma unroll
    for (int v = 0; v < 2; ++v) {
        const int i = i0 + ty;
        const int j = j0 + tx + 16 * v;
        keep[v] = (ti < tj) || (j > i);
        if (keep[v]) { s1 += l1a[v]; s2 += l2a[v]; }
    }

    {
        bred2(s1, s2, sbuf);
        if (tid == 0) {
            g_p1[blockIdx.x] = s1;
            g_p2[blockIdx.x] = s2;
            __threadfence();
            atomicAdd(&g_bar1, 1);
            while (*(volatile int*)&g_bar1 < GRID) {}
            __threadfence();
        }
        __syncthreads();   // release whole CTA; all partials visible
    }

    // bandwidth ladder from the 136 partials (fixed order -> deterministic)
    {
        float v1 = 0.0f, v2 = 0.0f;
        if (tid < GRID) {
            v1 = ((volatile float*)g_p1)[tid];
            v2 = ((volatile float*)g_p2)[tid];
        }
        bred2(v1, v2, sbuf);
        if (tid == 0) {
            const float cc = 2.0f * 0.01f / 261632.0f;   // 2/(N^2-N)/100
            float iv1 = -1.0f / (v1 * cc);               // negated ladder
            float iv2 = -1.0f / (v2 * cc);
#pragma unroll
            for (int m = 0; m < 5; ++m) {
                siv[m]     = iv1;
                siv[5 + m] = iv2;
                iv1 *= 0.1f;
                iv2 *= 0.1f;
            }
        }
        __syncthreads();
    }

    // exp phase straight from registers (scales pre-negated)
    float acc = 0.0f;
#pragma unroll
    for (int v = 0; v < 2; ++v) {
        if (keep[v]) {
            float kv = 0.0f;
#pragma unroll
            for (int m = 0; m < 5; ++m) {
                kv += __expf(l1a[v] * siv[m]);
                kv += __expf(l2a[v] * siv[5 + m]);
            }
            acc += kv;
        }
    }

    float atot = bred(acc, sbuf);
    if (tid == 0) {
        const float sgn = ((ti < 8) == (tj < 8)) ? 1.0f : -1.0f;
        g_p3[blockIdx.x] = sgn * atot;
        __threadfence();
        int r = atomicAdd(&g_bar2, 1);
        winflag = (r == GRID - 1);
    }
    __syncthreads();

    if (winflag) {
        // last-arriving CTA: everyone is past bar1 -> safe to finalize + reset
        float v = (tid < GRID) ? ((volatile float*)g_p3)[tid] : 0.0f;
        float s = bred(v, sbuf);
        if (tid == 0) {
            out[0] = 5120.0f / 65536.0f + s * (2.0f / 65536.0f);
            g_bar1 = 0;
            g_bar2 = 0;
            __threadfence();
        }
    }
}

extern "C" void kernel_launch(void* const* d_in, const int* in_sizes, int n_in,
                              void* d_out, int out_size) {
    const float* src = (const float*)d_in[0];
    const float* tgt = (const float*)d_in[1];
    float* out = (float*)d_out;
    mkmmd_kernel<<<GRID, NTHREAD>>>(src, tgt, out);
}

// round 15
// speedup vs baseline: 1.0309x; 1.0309x over previous
#include <cuda_runtime.h>
#include <cuda_fp16.h>

// MKMMD loss, fused persistent kernel (R15 = R14 at CH=128: 512 thr/CTA,
// 2x1 pairs/thread, 4 mainloop syncs instead of 8, per-thread prefetch kept
// at the validated 2xfloat4/matrix level). 136 CTAs, one 32x32 pair tile,
// full D=512, half2 math, fp16 accum flushed to fp32 every 64 k, distances
// register-resident across the device barrier, exp from registers.
// total = concat(src,tgt): N=512 rows, D=512.
// result = (10*N + 2*sum_{i<j} s_i s_j (kL2+kL1)) / B^2, s=+/-1 by half.
// bw_x = 2*S_upper_x/(N^2-N)/100 ; k = sum_{m=0..4} exp(-d/(bw*10^m))

#define DDIM    512
#define NTIL    16
#define GRID    136
#define NTHREAD 512
#define CH      128       // k-values per smem chunk (2 fp16 flush groups)
#define SWH     68        // row stride in half2 units: 272B = 17*16B (odd)
                          // -> conflict-free LDS.128, 16B-aligned rows

__device__ float g_p1[GRID];
__device__ float g_p2[GRID];
__device__ float g_p3[GRID];
__device__ int   g_bar1;
__device__ int   g_bar2;

// fused block reduce of two floats (512 thr); valid on thread 0 only
__device__ __forceinline__ void bred2(float& x, float& y, float* sbuf) {
    const int tid = threadIdx.x;
#pragma unroll
    for (int o = 16; o; o >>= 1) {
        x += __shfl_down_sync(0xffffffffu, x, o);
        y += __shfl_down_sync(0xffffffffu, y, o);
    }
    __syncthreads();                 // protect sbuf reuse across calls
    if ((tid & 31) == 0) {
        sbuf[2 * (tid >> 5)]     = x;
        sbuf[2 * (tid >> 5) + 1] = y;
    }
    __syncthreads();
    if (tid == 0) {
        float rx = 0.0f, ry = 0.0f;
#pragma unroll
        for (int w = 0; w < 16; ++w) { rx += sbuf[2 * w]; ry += sbuf[2 * w + 1]; }
        x = rx; y = ry;
    }
}

// single-value block reduce (512 thr); valid on thread 0 only
__device__ __forceinline__ float bred(float v, float* sbuf) {
    const int tid = threadIdx.x;
#pragma unroll
    for (int o = 16; o; o >>= 1) v += __shfl_down_sync(0xffffffffu, v, o);
    __syncthreads();
    if ((tid & 31) == 0) sbuf[tid >> 5] = v;
    __syncthreads();
    float r = 0.0f;
    if (tid == 0) {
#pragma unroll
        for (int w = 0; w < 16; ++w) r += sbuf[w];
    }
    return r;
}

__device__ __forceinline__ unsigned pk(float x, float y) {
    __half2 h = __floats2half2_rn(x, y);
    return *reinterpret_cast<unsigned*>(&h);
}
__device__ __forceinline__ __half2 uph(unsigned u) {
    return *reinterpret_cast<__half2*>(&u);
}

__global__ __launch_bounds__(NTHREAD, 1) void mkmmd_kernel(
    const float* __restrict__ src, const float* __restrict__ tgt,
    float* __restrict__ out)
{
    __shared__ __align__(16) unsigned As[2][32][SWH];   // half2 elements
    __shared__ __align__(16) unsigned Bs[2][32][SWH];
    __shared__ float sbuf[32];
    __shared__ float siv[10];       // NEGATED inverse-bandwidth ladders
    __shared__ int   winflag;

    const int tid = threadIdx.x;
    const int tx = tid & 15;        // B column 0..15 (pairs tx, tx+16)
    const int ty = tid >> 4;        // A row 0..31

    // decode upper-triangle tile (ti <= tj) over 16x16 grid of 32x32 tiles
    int t = blockIdx.x, ti = 0;
    while (t >= NTIL - ti) { t -= NTIL - ti; ti++; }
    const int tj = ti + t;
    const int i0 = ti * 32, j0 = tj * 32;
    const float* Ap = (i0 < 256) ? src + (size_t)i0 * DDIM : tgt + (size_t)(i0 - 256) * DDIM;
    const float* Bp = (j0 < 256) ? src + (size_t)j0 * DDIM : tgt + (size_t)(j0 - 256) * DDIM;

    // load assignment: row lr (0..31), 8 floats (-> 4 half2) at lcf
    const int lr  = tid >> 4;
    const int lcf = (tid & 15) * 8;       // float offset within 128-wide chunk
    const int lch = (tid & 15) * 4;       // half2 offset in smem row

    float l1a[2] = {0.f, 0.f};
    float l2a[2] = {0.f, 0.f};

    float4 pa0 = *(const float4*)(Ap + (size_t)lr * DDIM + lcf);
    float4 pa1 = *(const float4*)(Ap + (size_t)lr * DDIM + lcf + 4);
    float4 pb0 = *(const float4*)(Bp + (size_t)lr * DDIM + lcf);
    float4 pb1 = *(const float4*)(Bp + (size_t)lr * DDIM + lcf + 4);

    const int NCHUNK = DDIM / CH;   // 4
    for (int c = 0; c < NCHUNK; ++c) {
        const int p = c & 1;
        // convert prefetched floats to half2, one STS.128 per matrix
        {
            uint4 ua = make_uint4(pk(pa0.x, pa0.y), pk(pa0.z, pa0.w),
                                  pk(pa1.x, pa1.y), pk(pa1.z, pa1.w));
            uint4 ub = make_uint4(pk(pb0.x, pb0.y), pk(pb0.z, pb0.w),
                                  pk(pb1.x, pb1.y), pk(pb1.z, pb1.w));
            *(uint4*)&As[p][lr][lch] = ua;
            *(uint4*)&Bs[p][lr][lch] = ub;
        }
        __syncthreads();   // also guarantees compute(c-1) done before next STS

        if (c < NCHUNK - 1) {
            const int kb = (c + 1) * CH;
            pa0 = *(const float4*)(Ap + (size_t)lr * DDIM + kb + lcf);
            pa1 = *(const float4*)(Ap + (size_t)lr * DDIM + kb + lcf + 4);
            pb0 = *(const float4*)(Bp + (size_t)lr * DDIM + kb + lcf);
            pb1 = *(const float4*)(Bp + (size_t)lr * DDIM + kb + lcf + 4);
        }

        const uint4* ap  = (const uint4*)&As[p][ty][0];
        const uint4* b0p = (const uint4*)&Bs[p][tx][0];
        const uint4* b1p = (const uint4*)&Bs[p][tx + 16][0];

        // two fp16 accumulation groups of 64 k (validated chain length)
#pragma unroll
        for (int g = 0; g < 2; ++g) {
            __half2 h1[2], h2[2];
            const __half2 hz = __float2half2_rn(0.0f);
            h1[0] = hz; h1[1] = hz; h2[0] = hz; h2[1] = hz;

#pragma unroll
            for (int qq = 0; qq < 8; ++qq) {   // 8 k per q via LDS.128
                const int q = g * 8 + qq;
                uint4 A0 = ap[q], B0 = b0p[q], B1 = b1p[q];
                const unsigned au[4]  = {A0.x, A0.y, A0.z, A0.w};
                const unsigned bu0[4] = {B0.x, B0.y, B0.z, B0.w};
                const unsigned bu1[4] = {B1.x, B1.y, B1.z, B1.w};
#pragma unroll
                for (int h = 0; h < 4; ++h) {  // 2 k per h
                    __half2 av = uph(au[h]);
                    __half2 bv[2] = {uph(bu0[h]), uph(bu1[h])};
#pragma unroll
                    for (int v = 0; v < 2; ++v) {
                        __half2 d = __hsub2(av, bv[v]);       // HADD2 (fma)
                        h1[v] = __hadd2(h1[v], __habs2(d));   // LOP3 + HADD2
                        h2[v] = __hfma2(d, d, h2[v]);         // HFMA2 (fma)
                    }
                }
            }

            // flush group accumulators to fp32
#pragma unroll
            for (int v = 0; v < 2; ++v) {
                float2 f1 = __half22float2(h1[v]);
                float2 f2 = __half22float2(h2[v]);
                l1a[v] += f1.x + f1.y;
                l2a[v] += f2.x + f2.y;
            }
        }
    }

    // masked upper-triangle partial sums for bandwidth (dist stay in regs)
    bool keep[2];
    float s1 = 0.0f, s2 = 0.0f;
#pragma unroll
    for (int v = 0; v < 2; ++v) {
        const int i = i0 + ty;
        const int j = j0 + tx + 16 * v;
        keep[v] = (ti < tj) || (j > i);
        if (keep[v]) { s1 += l1a[v]; s2 += l2a[v]; }
    }

    {
        bred2(s1, s2, sbuf);
        if (tid == 0) {
            g_p1[blockIdx.x] = s1;
            g_p2[blockIdx.x] = s2;
            __threadfence();
            atomicAdd(&g_bar1, 1);
            while (*(volatile int*)&g_bar1 < GRID) {}
            __threadfence();
        }
        __syncthreads();   // release whole CTA; all partials visible
    }

    // bandwidth ladder from the 136 partials (fixed order -> deterministic)
    {
        float v1 = 0.0f, v2 = 0.0f;
        if (tid < GRID) {
            v1 = ((volatile float*)g_p1)[tid];
            v2 = ((volatile float*)g_p2)[tid];
        }
        bred2(v1, v2, sbuf);
        if (tid == 0) {
            const float cc = 2.0f * 0.01f / 261632.0f;   // 2/(N^2-N)/100
            float iv1 = -1.0f / (v1 * cc);               // negated ladder
            float iv2 = -1.0f / (v2 * cc);
#pragma unroll
            for (int m = 0; m < 5; ++m) {
                siv[m]     = iv1;
                siv[5 + m] = iv2;
                iv1 *= 0.1f;
                iv2 *= 0.1f;
            }
        }
        __syncthreads();
    }

    // exp phase straight from registers (scales pre-negated)
    float acc = 0.0f;
#pragma unroll
    for (int v = 0; v < 2; ++v) {
        if (keep[v]) {
            float kv = 0.0f;
#pragma unroll
            for (int m = 0; m < 5; ++m) {
                kv += __expf(l1a[v] * siv[m]);
                kv += __expf(l2a[v] * siv[5 + m]);
            }
            acc += kv;
        }
    }

    float atot = bred(acc, sbuf);
    if (tid == 0) {
        const float sgn = ((ti < 8) == (tj < 8)) ? 1.0f : -1.0f;
        g_p3[blockIdx.x] = sgn * atot;
        __threadfence();
        int r = atomicAdd(&g_bar2, 1);
        winflag = (r == GRID - 1);
    }
    __syncthreads();

    if (winflag) {
        // last-arriving CTA: everyone is past bar1 -> safe to finalize + reset
        float v = (tid < GRID) ? ((volatile float*)g_p3)[tid] : 0.0f;
        float s = bred(v, sbuf);
        if (tid == 0) {
            out[0] = 5120.0f / 65536.0f + s * (2.0f / 65536.0f);
            g_bar1 = 0;
            g_bar2 = 0;
            __threadfence();
        }
    }
}

extern "C" void kernel_launch(void* const* d_in, const int* in_sizes, int n_in,
                              void* d_out, int out_size) {
    const float* src = (const float*)d_in[0];
    const float* tgt = (const float*)d_in[1];
    float* out = (float*)d_out;
    mkmmd_kernel<<<GRID, NTHREAD>>>(src, tgt, out);
}

// round 16
// speedup vs baseline: 1.0811x; 1.0486x over previous
#include <cuda_runtime.h>
#include <cuda_fp16.h>

// MKMMD loss, fused persistent kernel (R16: L2 term via HMMA tensor-core dot,
// L1 term on fma pipe with 2 ops/half2; L2 = |a|^2+|b|^2-2dot, same identity
// as the reference). 136 CTAs, one 32x32 pair tile, full D=512, 256 threads,
// 8 warps = 2x4 grid of m16n8k16 warp tiles. fp16 L1 chains flushed per 64 k.
// total = concat(src,tgt): N=512 rows, D=512.
// result = (10*N + 2*sum_{i<j} s_i s_j (kL2+kL1)) / B^2, s=+/-1 by half.
// bw_x = 2*S_upper_x/(N^2-N)/100 ; k = sum_{m=0..4} exp(-d/(bw*10^m))

#define DDIM  512
#define NTIL  16
#define GRID  136
#define CH    64          // k-values per chunk (fp16 L1 chain length)
#define SWH   36          // row stride in half2 units: 144B = 9*16B (odd) ->
                          // conflict-free LDS.128, 16B-aligned rows

__device__ float g_p1[GRID];
__device__ float g_p2[GRID];
__device__ float g_p3[GRID];
__device__ int   g_bar1;
__device__ int   g_bar2;

// fused block reduce of two floats (256 thr); valid on thread 0 only
__device__ __forceinline__ void bred2(float& x, float& y, float* sbuf) {
    const int tid = threadIdx.x;
#pragma unroll
    for (int o = 16; o; o >>= 1) {
        x += __shfl_down_sync(0xffffffffu, x, o);
        y += __shfl_down_sync(0xffffffffu, y, o);
    }
    __syncthreads();
    if ((tid & 31) == 0) {
        sbuf[2 * (tid >> 5)]     = x;
        sbuf[2 * (tid >> 5) + 1] = y;
    }
    __syncthreads();
    if (tid == 0) {
        float rx = 0.0f, ry = 0.0f;
#pragma unroll
        for (int w = 0; w < 8; ++w) { rx += sbuf[2 * w]; ry += sbuf[2 * w + 1]; }
        x = rx; y = ry;
    }
}

// single-value block reduce (256 thr); valid on thread 0 only
__device__ __forceinline__ float bred(float v, float* sbuf) {
    const int tid = threadIdx.x;
#pragma unroll
    for (int o = 16; o; o >>= 1) v += __shfl_down_sync(0xffffffffu, v, o);
    __syncthreads();
    if ((tid & 31) == 0) sbuf[tid >> 5] = v;
    __syncthreads();
    float r = 0.0f;
    if (tid == 0) {
#pragma unroll
        for (int w = 0; w < 8; ++w) r += sbuf[w];
    }
    return r;
}

__device__ __forceinline__ unsigned pk(float x, float y) {
    __half2 h = __floats2half2_rn(x, y);
    return *reinterpret_cast<unsigned*>(&h);
}
__device__ __forceinline__ __half2 uph(unsigned u) {
    return *reinterpret_cast<__half2*>(&u);
}

// m16n8k16 row.col f16xf16 -> f32 accumulate
__device__ __forceinline__ void hmma16816(
    float& c0, float& c1, float& c2, float& c3,
    unsigned a0, unsigned a1, unsigned a2, unsigned a3,
    unsigned b0, unsigned b1)
{
    asm("mma.sync.aligned.m16n8k16.row.col.f32.f16.f16.f32 "
        "{%0,%1,%2,%3}, {%4,%5,%6,%7}, {%8,%9}, {%0,%1,%2,%3};"
        : "+f"(c0), "+f"(c1), "+f"(c2), "+f"(c3)
        : "r"(a0), "r"(a1), "r"(a2), "r"(a3), "r"(b0), "r"(b1));
}

__global__ __launch_bounds__(256, 1) void mkmmd_kernel(
    const float* __restrict__ src, const float* __restrict__ tgt,
    float* __restrict__ out)
{
    __shared__ __align__(16) unsigned As[2][32][SWH];   // half2 elements
    __shared__ __align__(16) unsigned Bs[2][32][SWH];
    __shared__ float sqA_s[32];
    __shared__ float sqB_s[32];
    __shared__ float sbuf[16];
    __shared__ float siv[10];       // NEGATED inverse-bandwidth ladders
    __shared__ int   winflag;

    const int tid  = threadIdx.x;
    const int wid  = tid >> 5;
    const int lane = tid & 31;
    const int g    = lane >> 2;     // group id 0..7
    const int t4   = lane & 3;      // thread-in-group 0..3
    const int wr   = wid >> 2;      // warp tile row 0..1 (16 rows each)
    const int wc   = wid & 3;       // warp tile col 0..3 (8 cols each)

    // this thread's 4 output pairs (C fragment layout of m16n8k16)
    const int iloc0 = wr * 16 + g;
    const int iloc1 = iloc0 + 8;
    const int jloc0 = wc * 8 + 2 * t4;
    const int jloc1 = jloc0 + 1;
    const int brow  = wc * 8 + g;   // B-fragment source row (n = g)

    // decode upper-triangle tile (ti <= tj) over 16x16 grid of 32x32 tiles
    int t = blockIdx.x, ti = 0;
    while (t >= NTIL - ti) { t -= NTIL - ti; ti++; }
    const int tj = ti + t;
    const int i0 = ti * 32, j0 = tj * 32;
    const float* Ap = (i0 < 256) ? src + (size_t)i0 * DDIM : tgt + (size_t)(i0 - 256) * DDIM;
    const float* Bp = (j0 < 256) ? src + (size_t)j0 * DDIM : tgt + (size_t)(j0 - 256) * DDIM;

    // load assignment: row lr (0..31), 8 floats (-> 4 half2) at lcf
    const int lr  = tid >> 3;
    const int lcf = (tid & 7) * 8;
    const int lch = (tid & 7) * 4;

    float c[4] = {0.f, 0.f, 0.f, 0.f};        // HMMA dot accumulators
    float l1f[4] = {0.f, 0.f, 0.f, 0.f};      // L1 fp32 accumulators
    float sqa = 0.f, sqb = 0.f;                // row-norm partials

    float4 pa0 = *(const float4*)(Ap + (size_t)lr * DDIM + lcf);
    float4 pa1 = *(const float4*)(Ap + (size_t)lr * DDIM + lcf + 4);
    float4 pb0 = *(const float4*)(Bp + (size_t)lr * DDIM + lcf);
    float4 pb1 = *(const float4*)(Bp + (size_t)lr * DDIM + lcf + 4);

    const int NCHUNK = DDIM / CH;   // 8
    for (int cc = 0; cc < NCHUNK; ++cc) {
        const int p = cc & 1;
        // convert prefetched floats to half2 + accumulate row norms (fp32)
        {
            uint4 ua = make_uint4(pk(pa0.x, pa0.y), pk(pa0.z, pa0.w),
                                  pk(pa1.x, pa1.y), pk(pa1.z, pa1.w));
            uint4 ub = make_uint4(pk(pb0.x, pb0.y), pk(pb0.z, pb0.w),
                                  pk(pb1.x, pb1.y), pk(pb1.z, pb1.w));
            *(uint4*)&As[p][lr][lch] = ua;
            *(uint4*)&Bs[p][lr][lch] = ub;
            // norms of the HALF-precision values (must match HMMA inputs)
            const unsigned* uap = &ua.x;
            const unsigned* ubp = &ub.x;
#pragma unroll
            for (int m = 0; m < 4; ++m) {
                float2 fa = __half22float2(uph(uap[m]));
                float2 fb = __half22float2(uph(ubp[m]));
                sqa = fmaf(fa.x, fa.x, sqa); sqa = fmaf(fa.y, fa.y, sqa);
                sqb = fmaf(fb.x, fb.x, sqb); sqb = fmaf(fb.y, fb.y, sqb);
            }
        }
        __syncthreads();

        if (cc < NCHUNK - 1) {
            const int kb = (cc + 1) * CH;
            pa0 = *(const float4*)(Ap + (size_t)lr * DDIM + kb + lcf);
            pa1 = *(const float4*)(Ap + (size_t)lr * DDIM + kb + lcf + 4);
            pb0 = *(const float4*)(Bp + (size_t)lr * DDIM + kb + lcf);
            pb1 = *(const float4*)(Bp + (size_t)lr * DDIM + kb + lcf + 4);
        }

        // ---- HMMA: 4 x k16 steps -> dot accumulates in c[] (tensor pipe) ----
#pragma unroll
        for (int s = 0; s < 4; ++s) {
            unsigned a0 = As[p][iloc0][s * 8 + t4];
            unsigned a1 = As[p][iloc1][s * 8 + t4];
            unsigned a2 = As[p][iloc0][s * 8 + 4 + t4];
            unsigned a3 = As[p][iloc1][s * 8 + 4 + t4];
            unsigned b0 = Bs[p][brow][s * 8 + t4];
            unsigned b1 = Bs[p][brow][s * 8 + 4 + t4];
            hmma16816(c[0], c[1], c[2], c[3], a0, a1, a2, a3, b0, b1);
        }

        // ---- L1: fp16 chains over this chunk's 64 k (2 fma ops / half2) ----
        __half2 h1[4];
        const __half2 hz = __float2half2_rn(0.0f);
        h1[0] = hz; h1[1] = hz; h1[2] = hz; h1[3] = hz;

        const uint4* aA0 = (const uint4*)&As[p][iloc0][0];
        const uint4* aA1 = (const uint4*)&As[p][iloc1][0];
        const uint4* bB0 = (const uint4*)&Bs[p][jloc0][0];
        const uint4* bB1 = (const uint4*)&Bs[p][jloc1][0];

#pragma unroll
        for (int q = 0; q < CH / 8; ++q) {     // 8 k per q via LDS.128
            uint4 A0 = aA0[q], A1 = aA1[q], B0 = bB0[q], B1 = bB1[q];
            const unsigned au0[4] = {A0.x, A0.y, A0.z, A0.w};
            const unsigned au1[4] = {A1.x, A1.y, A1.z, A1.w};
            const unsigned bu0[4] = {B0.x, B0.y, B0.z, B0.w};
            const unsigned bu1[4] = {B1.x, B1.y, B1.z, B1.w};
#pragma unroll
            for (int h = 0; h < 4; ++h) {      // 2 k per h
                __half2 av0 = uph(au0[h]), av1 = uph(au1[h]);
                __half2 bv0 = uph(bu0[h]), bv1 = uph(bu1[h]);
                h1[0] = __hadd2(h1[0], __habs2(__hsub2(av0, bv0)));
                h1[1] = __hadd2(h1[1], __habs2(__hsub2(av0, bv1)));
                h1[2] = __hadd2(h1[2], __habs2(__hsub2(av1, bv0)));
                h1[3] = __hadd2(h1[3], __habs2(__hsub2(av1, bv1)));
            }
        }
#pragma unroll
        for (int pp = 0; pp < 4; ++pp) {
            float2 f1 = __half22float2(h1[pp]);
            l1f[pp] += f1.x + f1.y;
        }
    }

    // ---- row norms: reduce the 8 threads sharing each row, publish ----
#pragma unroll
    for (int o = 4; o; o >>= 1) {
        sqa += __shfl_down_sync(0xffffffffu, sqa, o, 8);
        sqb += __shfl_down_sync(0xffffffffu, sqb, o, 8);
    }
    if ((tid & 7) == 0) { sqA_s[lr] = sqa; sqB_s[lr] = sqb; }
    __syncthreads();

    // ---- assemble L2 from norms + dot; masked partial sums ----
    float l2f[4];
    l2f[0] = sqA_s[iloc0] + sqB_s[jloc0] - 2.0f * c[0];
    l2f[1] = sqA_s[iloc0] + sqB_s[jloc1] - 2.0f * c[1];
    l2f[2] = sqA_s[iloc1] + sqB_s[jloc0] - 2.0f * c[2];
    l2f[3] = sqA_s[iloc1] + sqB_s[jloc1] - 2.0f * c[3];

    const int ig[4] = {i0 + iloc0, i0 + iloc0, i0 + iloc1, i0 + iloc1};
    const int jg[4] = {j0 + jloc0, j0 + jloc1, j0 + jloc0, j0 + jloc1};
    bool keep[4];
    float s1 = 0.f, s2 = 0.f;
#pragma unroll
    for (int pp = 0; pp < 4; ++pp) {
        keep[pp] = (ti < tj) || (jg[pp] > ig[pp]);
        if (keep[pp]) { s1 += l1f[pp]; s2 += l2f[pp]; }
    }

    {
        bred2(s1, s2, sbuf);
        if (tid == 0) {
            g_p1[blockIdx.x] = s1;
            g_p2[blockIdx.x] = s2;
            __threadfence();
            atomicAdd(&g_bar1, 1);
            while (*(volatile int*)&g_bar1 < GRID) {}
            __threadfence();
        }
        __syncthreads();   // release whole CTA; all partials visible
    }

    // bandwidth ladder from the 136 partials (fixed order -> deterministic)
    {
        float v1 = 0.0f, v2 = 0.0f;
        if (tid < GRID) {
            v1 = ((volatile float*)g_p1)[tid];
            v2 = ((volatile float*)g_p2)[tid];
        }
        bred2(v1, v2, sbuf);
        if (tid == 0) {
            const float ccn = 2.0f * 0.01f / 261632.0f;   // 2/(N^2-N)/100
            float iv1 = -1.0f / (v1 * ccn);               // negated ladder
            float iv2 = -1.0f / (v2 * ccn);
#pragma unroll
            for (int m = 0; m < 5; ++m) {
                siv[m]     = iv1;
                siv[5 + m] = iv2;
                iv1 *= 0.1f;
                iv2 *= 0.1f;
            }
        }
        __syncthreads();
    }

    // exp phase straight from registers (scales pre-negated)
    float acc = 0.0f;
#pragma unroll
    for (int pp = 0; pp < 4; ++pp) {
        if (keep[pp]) {
            float kv = 0.0f;
#pragma unroll
            for (int m = 0; m < 5; ++m) {
                kv += __expf(l1f[pp] * siv[m]);
                kv += __expf(l2f[pp] * siv[5 + m]);
            }
            acc += kv;
        }
    }

    float atot = bred(acc, sbuf);
    if (tid == 0) {
        const float sgn = ((ti < 8) == (tj < 8)) ? 1.0f : -1.0f;
        g_p3[blockIdx.x] = sgn * atot;
        __threadfence();
        int r = atomicAdd(&g_bar2, 1);
        winflag = (r == GRID - 1);
    }
    __syncthreads();

    if (winflag) {
        // last-arriving CTA: everyone is past bar1 -> safe to finalize + reset
        float v = (tid < GRID) ? ((volatile float*)g_p3)[tid] : 0.0f;
        float s = bred(v, sbuf);
        if (tid == 0) {
            out[0] = 5120.0f / 65536.0f + s * (2.0f / 65536.0f);
            g_bar1 = 0;
            g_bar2 = 0;
            __threadfence();
        }
    }
}

extern "C" void kernel_launch(void* const* d_in, const int* in_sizes, int n_in,
                              void* d_out, int out_size) {
    const float* src = (const float*)d_in[0];
    const float* tgt = (const float*)d_in[1];
    float* out = (float*)d_out;
    mkmmd_kernel<<<GRID, 256>>>(src, tgt, out);
}